// round 12
// baseline (speedup 1.0000x reference)
#include <cuda_runtime.h>
#include <cuda_fp16.h>
#include <cstdint>

#define IM 1024
#define NSEG 128
#define BLOCK 128   // render block (== NSEG)
#define PPT 8       // pixels per thread along y (4 half2 pairs)
#define NPAIR (PPT / 2)
#define CHUNK 8     // segments per half2-accumulation chunk (precision guard)
#define RGRID ((IM / BLOCK) * (IM / PPT))   // 1024 render blocks
#define NBLOCK 256  // normalize block
#define SCALE (1.0f / 64.0f)   // work in 1/64 px units (scale-invariant output)

// Scratch; fully rewritten each call, ticket wraps to 0 -> no init kernel.
__device__ float g_bmin[RGRID];
__device__ float g_bmax[RGRID];
__device__ float g_min_v;
__device__ float g_scale_v;
__device__ unsigned g_ticket;

// Rotated-frame per-segment constants (all broadcast half2):
//   u = xp*cx + yp*cy + ku      (along-segment coord, ku = -x0*cx - y0*cy)
//   v = xp*(-cy) + yp*cx + kv   (normal coord,        kv =  x0*cy - y0*cx)
//   d^2 = (u - clamp(u,0,L))^2 + v^2
struct __align__(16) SegA {     // one LDS.128 (broadcast)
    __half2 cx;
    __half2 cy;
    __half2 ku;
    __half2 kv;
};
struct __align__(8) SegB {      // one LDS.64 (broadcast)
    __half2 ncy;   // -cy
    __half2 L;     // segment length (scaled)
};

__global__ void __launch_bounds__(BLOCK, 7)
sk_render_kernel(const float* __restrict__ xs, const float* __restrict__ ys,
                 float* __restrict__ out) {
    __shared__ SegA sA[NSEG];
    __shared__ SegB sB[NSEG];
    __shared__ float s_wmin[BLOCK / 32], s_wmax[BLOCK / 32];
    __shared__ bool s_last;

    const int tid = threadIdx.x;

    {
        float x0 = xs[tid] * SCALE, x1 = xs[tid + 1] * SCALE;
        float y0 = ys[tid] * SCALE, y1 = ys[tid + 1] * SCALE;
        float dx = x1 - x0;
        float dy = y1 - y0;
        float L  = sqrtf(fmaf(dx, dx, dy * dy) + 1e-12f);
        float il = 1.0f / L;
        float cx = dx * il, cy = dy * il;
        SegA a;
        a.cx = __float2half2_rn(cx);
        a.cy = __float2half2_rn(cy);
        a.ku = __float2half2_rn(fmaf(-x0, cx, -y0 * cy));
        a.kv = __float2half2_rn(fmaf( x0, cy, -y0 * cx));
        sA[tid] = a;
        SegB b;
        b.ncy = __float2half2_rn(-cy);
        b.L   = __float2half2_rn(L);
        sB[tid] = b;
    }
    __syncthreads();

    // 8 blocks across x (128 cols), 128 block-rows across y (PPT=8 rows).
    const int bx = blockIdx.x & 7;
    const int by = blockIdx.x >> 3;
    const int x  = bx * BLOCK + tid;
    const int y0i = by * PPT;
    // x*SCALE = x/64 is exact in fp16 (multiple of 2^-6, <=10-bit mantissa)
    const __half2 xp2 = __float2half2_rn((float)x * SCALE);

    __half2 yp2[NPAIR];
    float acc[PPT];
#pragma unroll
    for (int p = 0; p < NPAIR; p++) {
        yp2[p] = __floats2half2_rn((float)(y0i + 2 * p) * SCALE,
                                   (float)(y0i + 2 * p + 1) * SCALE);
        acc[2 * p] = 0.0f; acc[2 * p + 1] = 0.0f;
    }

    const __half2 hzero = __float2half2_rn(0.0f);

#pragma unroll 2
    for (int kc = 0; kc < NSEG / CHUNK; kc++) {
        __half2 hacc[NPAIR];
#pragma unroll
        for (int p = 0; p < NPAIR; p++) hacc[p] = hzero;

#pragma unroll
        for (int kk = 0; kk < CHUNK; kk++) {
            const int k = kc * CHUNK + kk;
            const SegA a = sA[k];
            const SegB b = sB[k];
            // Fold xp into the affine constants (2 fma ops per k, amortized):
            const __half2 uc = __hfma2(xp2, a.cx,  a.ku);   // u = yp*cy + uc
            const __half2 vc = __hfma2(xp2, b.ncy, a.kv);   // v = yp*cx + vc

#pragma unroll
            for (int p = 0; p < NPAIR; p++) {
                __half2 u   = __hfma2(yp2[p], a.cy, uc);
                __half2 v   = __hfma2(yp2[p], a.cx, vc);
                __half2 ucl = __hmin2(__hmax2(u, hzero), b.L);  // alu pipe
                __half2 w   = __hsub2(u, ucl);   // exact 0 when unclamped
                __half2 vsq = __hmul2(v, v);
                __half2 d2  = __hfma2(w, w, vsq);
                hacc[p] = __hadd2(hacc[p], h2sqrt(d2));
            }
        }

        // Flush chunk: bit-expand fp16->fp32 (value * 2^-112 EXACTLY; uniform
        // factor cancels in min/max normalization), add into fp32 accumulators.
#pragma unroll
        for (int p = 0; p < NPAIR; p++) {
            unsigned v;
            __builtin_memcpy(&v, &hacc[p], 4);
            acc[2 * p]     += __uint_as_float((v << 13) & 0x0FFFE000u);
            acc[2 * p + 1] += __uint_as_float((v >> 3)  & 0x0FFFE000u);
        }
    }

    // Write raw sums + block min/max
    float lmin = acc[0], lmax = acc[0];
#pragma unroll
    for (int j = 0; j < PPT; j++) {
        out[(y0i + j) * IM + x] = acc[j];
        lmin = fminf(lmin, acc[j]);
        lmax = fmaxf(lmax, acc[j]);
    }
#pragma unroll
    for (int off = 16; off > 0; off >>= 1) {
        lmin = fminf(lmin, __shfl_xor_sync(0xFFFFFFFFu, lmin, off));
        lmax = fmaxf(lmax, __shfl_xor_sync(0xFFFFFFFFu, lmax, off));
    }
    const int lane = tid & 31;
    const int warp = tid >> 5;
    if (lane == 0) { s_wmin[warp] = lmin; s_wmax[warp] = lmax; }
    __syncthreads();
    if (tid == 0) {
        float bmin = s_wmin[0], bmax = s_wmax[0];
#pragma unroll
        for (int w = 1; w < BLOCK / 32; w++) {
            bmin = fminf(bmin, s_wmin[w]);
            bmax = fmaxf(bmax, s_wmax[w]);
        }
        g_bmin[blockIdx.x] = bmin;
        g_bmax[blockIdx.x] = bmax;
        __threadfence();
        unsigned ticket = atomicInc(&g_ticket, RGRID - 1);  // wraps -> deterministic
        s_last = (ticket == RGRID - 1);
    }
    __syncthreads();

    // Last-arriving block reduces the 1024 (min,max) pairs; normalize launch
    // is stream-ordered after us.
    if (s_last) {
        __threadfence();
        volatile float* vmin = g_bmin;
        volatile float* vmax = g_bmax;
        float m0 = vmin[tid], m1 = vmax[tid];
#pragma unroll
        for (int i = 1; i < RGRID / BLOCK; i++) {
            m0 = fminf(m0, vmin[tid + i * BLOCK]);
            m1 = fmaxf(m1, vmax[tid + i * BLOCK]);
        }
#pragma unroll
        for (int off = 16; off > 0; off >>= 1) {
            m0 = fminf(m0, __shfl_xor_sync(0xFFFFFFFFu, m0, off));
            m1 = fmaxf(m1, __shfl_xor_sync(0xFFFFFFFFu, m1, off));
        }
        if (lane == 0) { s_wmin[warp] = m0; s_wmax[warp] = m1; }
        __syncthreads();
        if (tid == 0) {
            float bmin = s_wmin[0], bmax = s_wmax[0];
#pragma unroll
            for (int w = 1; w < BLOCK / 32; w++) {
                bmin = fminf(bmin, s_wmin[w]);
                bmax = fmaxf(bmax, s_wmax[w]);
            }
            g_min_v   = bmin;
            g_scale_v = 1.0f / (bmax - bmin);
        }
    }
}

__global__ void __launch_bounds__(NBLOCK)
sk_normalize_kernel(float* __restrict__ out) {
    const float tmin = g_min_v;
    const float sc   = g_scale_v;
    const int i = blockIdx.x * NBLOCK + threadIdx.x;  // one float4 per thread
    float4* p = reinterpret_cast<float4*>(out) + i;
    float4 v = *p;
    v.x = (v.x - tmin) * sc;
    v.y = (v.y - tmin) * sc;
    v.z = (v.z - tmin) * sc;
    v.w = (v.w - tmin) * sc;
    *p = v;
}

extern "C" void kernel_launch(void* const* d_in, const int* in_sizes, int n_in,
                              void* d_out, int out_size) {
    const float* xs = (const float*)d_in[0];
    const float* ys = (const float*)d_in[1];
    float* out = (float*)d_out;

    sk_render_kernel<<<RGRID, BLOCK>>>(xs, ys, out);
    // 1M floats / (4 per thread * 256 threads) = 1024 blocks
    sk_normalize_kernel<<<(IM * IM) / (4 * NBLOCK), NBLOCK>>>(out);
}

// round 13
// speedup vs baseline: 1.0054x; 1.0054x over previous
#include <cuda_runtime.h>
#include <cuda_fp16.h>
#include <cstdint>

#define IM 1024
#define NSEG 128
#define BLOCK 128   // render block (== NSEG)
#define PPT 8       // pixels per thread along y (4 half2 pairs)
#define NPAIR (PPT / 2)
#define CHUNK 8     // segments per half2-accumulation chunk (precision guard)
#define RGRID ((IM / BLOCK) * (IM / PPT))   // 1024 blocks; all co-resident (7/SM)
#define SCALE (1.0f / 64.0f)   // work in 1/64 px units (scale-invariant output)

// Scratch; bmin/bmax fully rewritten each call, ticket wraps to 0, gen is a
// monotone generation counter -> no init kernel, deterministic across replays.
__device__ float g_bmin[RGRID];
__device__ float g_bmax[RGRID];
__device__ float g_min_v;
__device__ float g_scale_v;
__device__ unsigned g_ticket;
__device__ unsigned g_gen;

struct __align__(16) SegA {     // one LDS.128 (broadcast)
    __half2 nx0;   // broadcast(-x0*S)
    __half2 ny0;   // broadcast(-y0*S)
    __half2 dxi;   // broadcast(dx*invd)
    __half2 dyi;   // broadcast(dy*invd)
};
struct __align__(8) SegB {      // one LDS.64 (broadcast)
    __half2 ndx;   // broadcast(-dx*S)
    __half2 ndy;   // broadcast(-dy*S)
};

__global__ void __launch_bounds__(BLOCK, 7)
sk_kernel(const float* __restrict__ xs, const float* __restrict__ ys,
          float* __restrict__ out) {
    __shared__ SegA sA[NSEG];
    __shared__ SegB sB[NSEG];
    __shared__ float s_wmin[BLOCK / 32], s_wmax[BLOCK / 32];
    __shared__ unsigned s_gen0;
    __shared__ bool s_last;
    __shared__ float s_tmin, s_sc;

    const int tid = threadIdx.x;
    if (tid == 0) s_gen0 = *(volatile unsigned*)&g_gen;

    {
        float x0 = xs[tid] * SCALE, x1 = xs[tid + 1] * SCALE;
        float y0 = ys[tid] * SCALE, y1 = ys[tid + 1] * SCALE;
        float dx = x1 - x0;
        float dy = y1 - y0;
        float invd = 1.0f / (fmaf(dx, dx, dy * dy) + 1e-12f);
        SegA a;
        a.nx0 = __float2half2_rn(-x0);
        a.ny0 = __float2half2_rn(-y0);
        a.dxi = __float2half2_rn(dx * invd);
        a.dyi = __float2half2_rn(dy * invd);
        sA[tid] = a;
        SegB b;
        b.ndx = __float2half2_rn(-dx);
        b.ndy = __float2half2_rn(-dy);
        sB[tid] = b;
    }
    __syncthreads();

    // 8 blocks across x (128 cols), 128 block-rows across y (PPT=8 rows).
    const int bx = blockIdx.x & 7;
    const int by = blockIdx.x >> 3;
    const int x  = bx * BLOCK + tid;
    const int y0i = by * PPT;
    // x*SCALE = x/64 is exact in fp16 (multiple of 2^-6, <=10-bit mantissa)
    const __half2 xp2 = __float2half2_rn((float)x * SCALE);

    __half2 yp2[NPAIR];
    float acc[PPT];
#pragma unroll
    for (int p = 0; p < NPAIR; p++) {
        yp2[p] = __floats2half2_rn((float)(y0i + 2 * p) * SCALE,
                                   (float)(y0i + 2 * p + 1) * SCALE);
        acc[2 * p] = 0.0f; acc[2 * p + 1] = 0.0f;
    }

    const __half2 hzero = __float2half2_rn(0.0f);

#pragma unroll 2
    for (int kc = 0; kc < NSEG / CHUNK; kc++) {
        __half2 hacc[NPAIR];
#pragma unroll
        for (int p = 0; p < NPAIR; p++) hacc[p] = hzero;

#pragma unroll
        for (int kk = 0; kk < CHUNK; kk++) {
            const int k = kc * CHUNK + kk;
            const SegA a = sA[k];
            const SegB b = sB[k];
            const __half2 xd = __hadd2(xp2, a.nx0);     // xp - x0
            const __half2 q  = __hmul2(xd, a.dxi);      // (xp-x0)*dx*invd

#pragma unroll
            for (int p = 0; p < NPAIR; p++) {
                __half2 yd = __hadd2(yp2[p], a.ny0);            // yp - y0
                __half2 t  = __hfma2_sat(yd, a.dyi, q);         // clamp(t,0,1)
                __half2 ex = __hfma2(t, b.ndx, xd);             // xp - (x0+t*dx)
                __half2 ey = __hfma2(t, b.ndy, yd);             // yp - (y0+t*dy)
                __half2 dq = __hmul2(ey, ey);
                __half2 d2 = __hfma2(ex, ex, dq);
                hacc[p] = __hadd2(hacc[p], h2sqrt(d2));         // half2 accumulate
            }
        }

        // Flush chunk: bit-expand fp16->fp32 (value * 2^-112 EXACTLY; uniform
        // factor cancels in min/max normalization), add into fp32 accumulators.
#pragma unroll
        for (int p = 0; p < NPAIR; p++) {
            unsigned v;
            __builtin_memcpy(&v, &hacc[p], 4);
            acc[2 * p]     += __uint_as_float((v << 13) & 0x0FFFE000u);
            acc[2 * p + 1] += __uint_as_float((v >> 3)  & 0x0FFFE000u);
        }
    }

    // Block min/max over registers
    float lmin = acc[0], lmax = acc[0];
#pragma unroll
    for (int j = 1; j < PPT; j++) {
        lmin = fminf(lmin, acc[j]);
        lmax = fmaxf(lmax, acc[j]);
    }
#pragma unroll
    for (int off = 16; off > 0; off >>= 1) {
        lmin = fminf(lmin, __shfl_xor_sync(0xFFFFFFFFu, lmin, off));
        lmax = fmaxf(lmax, __shfl_xor_sync(0xFFFFFFFFu, lmax, off));
    }
    const int lane = tid & 31;
    const int warp = tid >> 5;
    if (lane == 0) { s_wmin[warp] = lmin; s_wmax[warp] = lmax; }
    __syncthreads();
    if (tid == 0) {
        float bmin = s_wmin[0], bmax = s_wmax[0];
#pragma unroll
        for (int w = 1; w < BLOCK / 32; w++) {
            bmin = fminf(bmin, s_wmin[w]);
            bmax = fmaxf(bmax, s_wmax[w]);
        }
        g_bmin[blockIdx.x] = bmin;
        g_bmax[blockIdx.x] = bmax;
        __threadfence();
        unsigned ticket = atomicInc(&g_ticket, RGRID - 1);  // wraps -> deterministic
        s_last = (ticket == RGRID - 1);
    }
    __syncthreads();

    if (s_last) {
        // Last-arriving block reduces all 1024 (min,max) pairs, releases gen.
        __threadfence();
        volatile float* vmin = g_bmin;
        volatile float* vmax = g_bmax;
        float m0 = vmin[tid], m1 = vmax[tid];
#pragma unroll
        for (int i = 1; i < RGRID / BLOCK; i++) {
            m0 = fminf(m0, vmin[tid + i * BLOCK]);
            m1 = fmaxf(m1, vmax[tid + i * BLOCK]);
        }
#pragma unroll
        for (int off = 16; off > 0; off >>= 1) {
            m0 = fminf(m0, __shfl_xor_sync(0xFFFFFFFFu, m0, off));
            m1 = fmaxf(m1, __shfl_xor_sync(0xFFFFFFFFu, m1, off));
        }
        if (lane == 0) { s_wmin[warp] = m0; s_wmax[warp] = m1; }
        __syncthreads();
        if (tid == 0) {
            float bmin = s_wmin[0], bmax = s_wmax[0];
#pragma unroll
            for (int w = 1; w < BLOCK / 32; w++) {
                bmin = fminf(bmin, s_wmin[w]);
                bmax = fmaxf(bmax, s_wmax[w]);
            }
            *(volatile float*)&g_min_v   = bmin;
            *(volatile float*)&g_scale_v = 1.0f / (bmax - bmin);
            __threadfence();
            *(volatile unsigned*)&g_gen = s_gen0 + 1;  // release
        }
        __syncthreads();
    }

    // All blocks: wait for the generation bump (all 1024 blocks co-resident
    // per __launch_bounds__(128,7): 148*7 = 1036 >= 1024), fetch (tmin, sc).
    if (tid == 0) {
        const unsigned gen0 = s_gen0;
        while (*(volatile unsigned*)&g_gen == gen0) { __nanosleep(32); }
        __threadfence();
        s_tmin = *(volatile float*)&g_min_v;
        s_sc   = *(volatile float*)&g_scale_v;
    }
    __syncthreads();

    // Normalized write directly from registers (only store, no reload pass).
    const float tmin = s_tmin;
    const float sc   = s_sc;
#pragma unroll
    for (int j = 0; j < PPT; j++) {
        out[(y0i + j) * IM + x] = (acc[j] - tmin) * sc;
    }
}

extern "C" void kernel_launch(void* const* d_in, const int* in_sizes, int n_in,
                              void* d_out, int out_size) {
    const float* xs = (const float*)d_in[0];
    const float* ys = (const float*)d_in[1];
    float* out = (float*)d_out;
    sk_kernel<<<RGRID, BLOCK>>>(xs, ys, out);
}